// round 1
// baseline (speedup 1.0000x reference)
#include <cuda_runtime.h>
#include <cstdint>

#define NUM_EXPERTS 8
#define HIDDEN 2048
#define EXPERT_DIM 4096
#define TOKENS 1024

// Scratch for gated activations [E, T, I] (fp32). Static __device__ per harness rules.
__device__ float g_act[(size_t)NUM_EXPERTS * TOKENS * EXPERT_DIM];

__device__ __forceinline__ uint32_t f2tf32(float x) {
    uint32_t r;
    asm("cvt.rna.tf32.f32 %0, %1;" : "=r"(r) : "f"(x));
    return r;
}

__device__ __forceinline__ void mma_tf32(float* c, const uint32_t* a, const uint32_t* b) {
    asm volatile(
        "mma.sync.aligned.m16n8k8.row.col.f32.tf32.tf32.f32 "
        "{%0,%1,%2,%3}, {%4,%5,%6,%7}, {%8,%9}, {%0,%1,%2,%3};\n"
        : "+f"(c[0]), "+f"(c[1]), "+f"(c[2]), "+f"(c[3])
        : "r"(a[0]), "r"(a[1]), "r"(a[2]), "r"(a[3]), "r"(b[0]), "r"(b[1]));
}

// ---------------------------------------------------------------------------
// GEMM1 fused with silu-gating.
// Per expert e: C_gate = X[e] @ W1[e][:, n], C_up = X[e] @ W1[e][:, n+4096]
// G[e] = C_up * silu(C_gate)
// Block tile: M=128, N=64 (gated cols), BK=16. 256 threads = 8 warps (4 M x 2 N),
// warp tile 32x32 per output matrix.
// ---------------------------------------------------------------------------
__global__ __launch_bounds__(256) void gemm1_silu_kernel(
    const float* __restrict__ X,    // [E*T, H]
    const float* __restrict__ W1)   // [E, H, 2I]
{
    const int e  = blockIdx.z;
    const int m0 = blockIdx.y * 128;
    const int n0 = blockIdx.x * 64;

    const int tid  = threadIdx.x;
    const int warp = tid >> 5;
    const int lane = tid & 31;
    const int wm = (warp >> 1) * 32;   // warp M offset (4 warps in M)
    const int wn = (warp & 1) * 32;    // warp N offset (2 warps in N)
    const int g  = lane >> 2;          // groupID
    const int tg = lane & 3;           // thread-in-group

    // Padded strides: 20 and 72 words -> k-row offsets distinct mod 32 banks,
    // and every float4 store offset is 16B aligned.
    __shared__ uint32_t As[2][128][20];
    __shared__ uint32_t Bg[2][16][72];
    __shared__ uint32_t Bu[2][16][72];

    const float* Aptr  = X  + (size_t)(e * TOKENS + m0) * HIDDEN;
    const float* Bgptr = W1 + (size_t)e * HIDDEN * (2 * EXPERT_DIM) + n0;
    const float* Buptr = Bgptr + EXPERT_DIM;

    // Staging thread mapping
    const int ar = tid >> 2;         // 0..63 (A rows; also row+64)
    const int ac = (tid & 3) * 4;    // 0,4,8,12
    const int bk = tid >> 4;         // 0..15 (B k-row)
    const int bn = (tid & 15) * 4;   // 0..60

    float4 ra0, ra1, rg, ru;

    // Prologue: load tile 0
    {
        const float* a = Aptr;
        ra0 = *(const float4*)(a + (size_t)ar * HIDDEN + ac);
        ra1 = *(const float4*)(a + (size_t)(ar + 64) * HIDDEN + ac);
        rg  = *(const float4*)(Bgptr + (size_t)bk * (2 * EXPERT_DIM) + bn);
        ru  = *(const float4*)(Buptr + (size_t)bk * (2 * EXPERT_DIM) + bn);
        As[0][ar][ac + 0]      = f2tf32(ra0.x);
        As[0][ar][ac + 1]      = f2tf32(ra0.y);
        As[0][ar][ac + 2]      = f2tf32(ra0.z);
        As[0][ar][ac + 3]      = f2tf32(ra0.w);
        As[0][ar + 64][ac + 0] = f2tf32(ra1.x);
        As[0][ar + 64][ac + 1] = f2tf32(ra1.y);
        As[0][ar + 64][ac + 2] = f2tf32(ra1.z);
        As[0][ar + 64][ac + 3] = f2tf32(ra1.w);
        Bg[0][bk][bn + 0] = f2tf32(rg.x);
        Bg[0][bk][bn + 1] = f2tf32(rg.y);
        Bg[0][bk][bn + 2] = f2tf32(rg.z);
        Bg[0][bk][bn + 3] = f2tf32(rg.w);
        Bu[0][bk][bn + 0] = f2tf32(ru.x);
        Bu[0][bk][bn + 1] = f2tf32(ru.y);
        Bu[0][bk][bn + 2] = f2tf32(ru.z);
        Bu[0][bk][bn + 3] = f2tf32(ru.w);
    }
    __syncthreads();

    float accg[2][4][4] = {};
    float accu[2][4][4] = {};

    const int nT = HIDDEN / 16;
    for (int kt = 0; kt < nT; ++kt) {
        const int buf = kt & 1;
        if (kt + 1 < nT) {
            const float* a = Aptr + (kt + 1) * 16;
            ra0 = *(const float4*)(a + (size_t)ar * HIDDEN + ac);
            ra1 = *(const float4*)(a + (size_t)(ar + 64) * HIDDEN + ac);
            rg  = *(const float4*)(Bgptr + (size_t)((kt + 1) * 16 + bk) * (2 * EXPERT_DIM) + bn);
            ru  = *(const float4*)(Buptr + (size_t)((kt + 1) * 16 + bk) * (2 * EXPERT_DIM) + bn);
        }

        #pragma unroll
        for (int ks = 0; ks < 2; ++ks) {
            const int k8 = ks * 8;
            uint32_t af[2][4];
            #pragma unroll
            for (int im = 0; im < 2; ++im) {
                const int r = wm + im * 16 + g;
                af[im][0] = As[buf][r][k8 + tg];
                af[im][1] = As[buf][r + 8][k8 + tg];
                af[im][2] = As[buf][r][k8 + tg + 4];
                af[im][3] = As[buf][r + 8][k8 + tg + 4];
            }
            uint32_t bgf[4][2], buf2[4][2];
            #pragma unroll
            for (int in = 0; in < 4; ++in) {
                const int c = wn + in * 8 + g;
                bgf[in][0]  = Bg[buf][k8 + tg][c];
                bgf[in][1]  = Bg[buf][k8 + tg + 4][c];
                buf2[in][0] = Bu[buf][k8 + tg][c];
                buf2[in][1] = Bu[buf][k8 + tg + 4][c];
            }
            #pragma unroll
            for (int im = 0; im < 2; ++im) {
                #pragma unroll
                for (int in = 0; in < 4; ++in) {
                    mma_tf32(accg[im][in], af[im], bgf[in]);
                    mma_tf32(accu[im][in], af[im], buf2[in]);
                }
            }
        }

        if (kt + 1 < nT) {
            const int nb = (kt + 1) & 1;
            As[nb][ar][ac + 0]      = f2tf32(ra0.x);
            As[nb][ar][ac + 1]      = f2tf32(ra0.y);
            As[nb][ar][ac + 2]      = f2tf32(ra0.z);
            As[nb][ar][ac + 3]      = f2tf32(ra0.w);
            As[nb][ar + 64][ac + 0] = f2tf32(ra1.x);
            As[nb][ar + 64][ac + 1] = f2tf32(ra1.y);
            As[nb][ar + 64][ac + 2] = f2tf32(ra1.z);
            As[nb][ar + 64][ac + 3] = f2tf32(ra1.w);
            Bg[nb][bk][bn + 0] = f2tf32(rg.x);
            Bg[nb][bk][bn + 1] = f2tf32(rg.y);
            Bg[nb][bk][bn + 2] = f2tf32(rg.z);
            Bg[nb][bk][bn + 3] = f2tf32(rg.w);
            Bu[nb][bk][bn + 0] = f2tf32(ru.x);
            Bu[nb][bk][bn + 1] = f2tf32(ru.y);
            Bu[nb][bk][bn + 2] = f2tf32(ru.z);
            Bu[nb][bk][bn + 3] = f2tf32(ru.w);
        }
        __syncthreads();
    }

    // Epilogue: gated = up * silu(gate), write to scratch
    float* Gout = g_act + (size_t)e * TOKENS * EXPERT_DIM + (size_t)m0 * EXPERT_DIM + n0;
    #pragma unroll
    for (int im = 0; im < 2; ++im) {
        #pragma unroll
        for (int in = 0; in < 4; ++in) {
            #pragma unroll
            for (int h = 0; h < 2; ++h) {
                const int r = wm + im * 16 + g + h * 8;
                const int c = wn + in * 8 + 2 * tg;
                const float gv0 = accg[im][in][h * 2 + 0];
                const float gv1 = accg[im][in][h * 2 + 1];
                const float uv0 = accu[im][in][h * 2 + 0];
                const float uv1 = accu[im][in][h * 2 + 1];
                const float s0 = gv0 / (1.0f + __expf(-gv0));
                const float s1 = gv1 / (1.0f + __expf(-gv1));
                *(float2*)(Gout + (size_t)r * EXPERT_DIM + c) = make_float2(uv0 * s0, uv1 * s1);
            }
        }
    }
}

// ---------------------------------------------------------------------------
// GEMM2: Out[e] = G[e] (1024x4096) @ W2[e] (4096x2048)
// Block tile: M=128, N=128, BK=16. 256 threads = 8 warps (2 M x 4 N),
// warp tile 64x32.
// ---------------------------------------------------------------------------
__global__ __launch_bounds__(256) void gemm2_kernel(
    const float* __restrict__ W2,   // [E, I, H]
    float* __restrict__ Out)        // [E*T, H]
{
    const int e  = blockIdx.z;
    const int m0 = blockIdx.y * 128;
    const int n0 = blockIdx.x * 128;

    const int tid  = threadIdx.x;
    const int warp = tid >> 5;
    const int lane = tid & 31;
    const int wm = (warp >> 2) * 64;   // 2 warps in M
    const int wn = (warp & 3) * 32;    // 4 warps in N
    const int g  = lane >> 2;
    const int tg = lane & 3;

    __shared__ uint32_t As[2][128][20];
    __shared__ uint32_t Bs[2][16][136];  // 136 words: k-rows spread 8 banks apart, 16B aligned

    const float* Aptr = g_act + (size_t)e * TOKENS * EXPERT_DIM + (size_t)m0 * EXPERT_DIM;
    const float* Bptr = W2 + (size_t)e * EXPERT_DIM * HIDDEN + n0;

    const int ar = tid >> 2;          // 0..63 (+64)
    const int ac = (tid & 3) * 4;
    const int bk = tid >> 5;          // 0..7 (+8)
    const int bn = (tid & 31) * 4;    // 0..124

    float4 ra0, ra1, rb0, rb1;

    {
        ra0 = *(const float4*)(Aptr + (size_t)ar * EXPERT_DIM + ac);
        ra1 = *(const float4*)(Aptr + (size_t)(ar + 64) * EXPERT_DIM + ac);
        rb0 = *(const float4*)(Bptr + (size_t)bk * HIDDEN + bn);
        rb1 = *(const float4*)(Bptr + (size_t)(bk + 8) * HIDDEN + bn);
        As[0][ar][ac + 0]      = f2tf32(ra0.x);
        As[0][ar][ac + 1]      = f2tf32(ra0.y);
        As[0][ar][ac + 2]      = f2tf32(ra0.z);
        As[0][ar][ac + 3]      = f2tf32(ra0.w);
        As[0][ar + 64][ac + 0] = f2tf32(ra1.x);
        As[0][ar + 64][ac + 1] = f2tf32(ra1.y);
        As[0][ar + 64][ac + 2] = f2tf32(ra1.z);
        As[0][ar + 64][ac + 3] = f2tf32(ra1.w);
        Bs[0][bk][bn + 0]     = f2tf32(rb0.x);
        Bs[0][bk][bn + 1]     = f2tf32(rb0.y);
        Bs[0][bk][bn + 2]     = f2tf32(rb0.z);
        Bs[0][bk][bn + 3]     = f2tf32(rb0.w);
        Bs[0][bk + 8][bn + 0] = f2tf32(rb1.x);
        Bs[0][bk + 8][bn + 1] = f2tf32(rb1.y);
        Bs[0][bk + 8][bn + 2] = f2tf32(rb1.z);
        Bs[0][bk + 8][bn + 3] = f2tf32(rb1.w);
    }
    __syncthreads();

    float acc[4][4][4] = {};

    const int nT = EXPERT_DIM / 16;
    for (int kt = 0; kt < nT; ++kt) {
        const int buf = kt & 1;
        if (kt + 1 < nT) {
            const float* a = Aptr + (kt + 1) * 16;
            ra0 = *(const float4*)(a + (size_t)ar * EXPERT_DIM + ac);
            ra1 = *(const float4*)(a + (size_t)(ar + 64) * EXPERT_DIM + ac);
            rb0 = *(const float4*)(Bptr + (size_t)((kt + 1) * 16 + bk) * HIDDEN + bn);
            rb1 = *(const float4*)(Bptr + (size_t)((kt + 1) * 16 + bk + 8) * HIDDEN + bn);
        }

        #pragma unroll
        for (int ks = 0; ks < 2; ++ks) {
            const int k8 = ks * 8;
            uint32_t af[4][4];
            #pragma unroll
            for (int im = 0; im < 4; ++im) {
                const int r = wm + im * 16 + g;
                af[im][0] = As[buf][r][k8 + tg];
                af[im][1] = As[buf][r + 8][k8 + tg];
                af[im][2] = As[buf][r][k8 + tg + 4];
                af[im][3] = As[buf][r + 8][k8 + tg + 4];
            }
            uint32_t bf[4][2];
            #pragma unroll
            for (int in = 0; in < 4; ++in) {
                const int c = wn + in * 8 + g;
                bf[in][0] = Bs[buf][k8 + tg][c];
                bf[in][1] = Bs[buf][k8 + tg + 4][c];
            }
            #pragma unroll
            for (int im = 0; im < 4; ++im) {
                #pragma unroll
                for (int in = 0; in < 4; ++in) {
                    mma_tf32(acc[im][in], af[im], bf[in]);
                }
            }
        }

        if (kt + 1 < nT) {
            const int nb = (kt + 1) & 1;
            As[nb][ar][ac + 0]      = f2tf32(ra0.x);
            As[nb][ar][ac + 1]      = f2tf32(ra0.y);
            As[nb][ar][ac + 2]      = f2tf32(ra0.z);
            As[nb][ar][ac + 3]      = f2tf32(ra0.w);
            As[nb][ar + 64][ac + 0] = f2tf32(ra1.x);
            As[nb][ar + 64][ac + 1] = f2tf32(ra1.y);
            As[nb][ar + 64][ac + 2] = f2tf32(ra1.z);
            As[nb][ar + 64][ac + 3] = f2tf32(ra1.w);
            Bs[nb][bk][bn + 0]     = f2tf32(rb0.x);
            Bs[nb][bk][bn + 1]     = f2tf32(rb0.y);
            Bs[nb][bk][bn + 2]     = f2tf32(rb0.z);
            Bs[nb][bk][bn + 3]     = f2tf32(rb0.w);
            Bs[nb][bk + 8][bn + 0] = f2tf32(rb1.x);
            Bs[nb][bk + 8][bn + 1] = f2tf32(rb1.y);
            Bs[nb][bk + 8][bn + 2] = f2tf32(rb1.z);
            Bs[nb][bk + 8][bn + 3] = f2tf32(rb1.w);
        }
        __syncthreads();
    }

    float* Optr = Out + (size_t)(e * TOKENS + m0) * HIDDEN + n0;
    #pragma unroll
    for (int im = 0; im < 4; ++im) {
        #pragma unroll
        for (int in = 0; in < 4; ++in) {
            #pragma unroll
            for (int h = 0; h < 2; ++h) {
                const int r = wm + im * 16 + g + h * 8;
                const int c = wn + in * 8 + 2 * tg;
                *(float2*)(Optr + (size_t)r * HIDDEN + c) =
                    make_float2(acc[im][in][h * 2 + 0], acc[im][in][h * 2 + 1]);
            }
        }
    }
}

extern "C" void kernel_launch(void* const* d_in, const int* in_sizes, int n_in,
                              void* d_out, int out_size) {
    const float* X  = (const float*)d_in[0];   // hidden_states [8192, 2048]
    const float* W1 = (const float*)d_in[1];   // gate_up_proj  [8, 2048, 8192]
    const float* W2 = (const float*)d_in[2];   // down_proj     [8, 4096, 2048]
    float* Out = (float*)d_out;                // [8192, 2048]

    dim3 blk(256);
    dim3 g1(EXPERT_DIM / 64, TOKENS / 128, NUM_EXPERTS);   // 64 x 8 x 8
    dim3 g2(HIDDEN / 128, TOKENS / 128, NUM_EXPERTS);      // 16 x 8 x 8
    gemm1_silu_kernel<<<g1, blk>>>(X, W1);
    gemm2_kernel<<<g2, blk>>>(W2, Out);
}